// round 3
// baseline (speedup 1.0000x reference)
#include <cuda_runtime.h>
#include <cuda_bf16.h>
#include <cstdint>

// Problem constants (fixed by the dataset)
#define K_DIM 256
#define N_DIM 64
#define MAX_NODES 100000

// Scratch for pre_sup = X @ W  (no cudaMalloc allowed)
__device__ float g_pre[(size_t)MAX_NODES * N_DIM];
// Index-dtype flag: 1 if indices are int64, 0 if int32
__device__ int g_idx64;

// ---------------------------------------------------------------------------
// Kernel 0a/0b: detect index dtype (parallel). int64 non-negative values
// < 2^31 have all-zero high 32-bit words; int32 data at odd word positions
// holds real (mostly nonzero) indices.
// ---------------------------------------------------------------------------
__global__ void set_flag_kernel() { g_idx64 = 1; }

__global__ void detect_idx_kernel(const unsigned int* __restrict__ rows_u32, int E)
{
    int n = E < 4096 ? E : 4096;
    int i = blockIdx.x * blockDim.x + threadIdx.x;
    if (i < n && rows_u32[2 * i + 1] != 0u)
        g_idx64 = 0;   // benign race: all writers store 0
}

// ---------------------------------------------------------------------------
// Kernel 1: GEMM  pre_sup[M,64] = X[M,256] @ W[256,64]
// 128 threads, tile 128(M) x 64(N), thread tile 8x8, BK=32.
// Inner loop uses packed fp32x2 FMAs (fma.rn.f32x2): accumulators paired over
// adjacent rows (lo=row 2i, hi=row 2i+1); B values pre-duplicated in smem.
// ---------------------------------------------------------------------------
#define BM 128
#define BK 32
#define AS_LD (BM + 4)              // row stride in floats; keeps 16B alignment
#define BG_LD (BK * 8 + 2)          // BsDup group stride in u64 (2064B: banks spread)

__device__ __forceinline__ unsigned long long dup2(float f)
{
    unsigned int u = __float_as_uint(f);
    return ((unsigned long long)u << 32) | (unsigned long long)u;
}

__device__ __forceinline__ void fma_f32x2(unsigned long long& d,
                                          unsigned long long a,
                                          unsigned long long b)
{
    asm("fma.rn.f32x2 %0, %1, %2, %0;" : "+l"(d) : "l"(a), "l"(b));
}

__global__ void __launch_bounds__(128, 5) gemm_kernel(
    const float* __restrict__ x, const float* __restrict__ w, int M)
{
    __shared__ float As[BK][AS_LD];                     // transposed: [k][row]
    __shared__ unsigned long long BsDup[8][BG_LD];      // [col group][k*8 + col%8]

    const int tid = threadIdx.x;
    const int tx  = tid & 7;    // col group: cols tx*8 .. tx*8+7
    const int ty  = tid >> 3;   // row group: rows ty*8 .. ty*8+7 (0..15)
    const int rowBase = blockIdx.x * BM;

    // acc2[i2][j]: lo = acc[2*i2][j], hi = acc[2*i2+1][j]
    unsigned long long acc2[4][8];
#pragma unroll
    for (int i = 0; i < 4; i++)
#pragma unroll
        for (int j = 0; j < 8; j++) acc2[i][j] = 0ull;

    for (int kb = 0; kb < K_DIM; kb += BK) {
        // ---- load A tile (transposed into As[k][row])
#pragma unroll
        for (int i = 0; i < 8; i++) {
            int r  = i * 16 + (tid >> 3);
            int kk = (tid & 7) * 4;
            int gr = rowBase + r;
            float4 v = make_float4(0.f, 0.f, 0.f, 0.f);
            if (gr < M)
                v = *(const float4*)(x + (size_t)gr * K_DIM + kb + kk);
            As[kk + 0][r] = v.x;
            As[kk + 1][r] = v.y;
            As[kk + 2][r] = v.z;
            As[kk + 3][r] = v.w;
        }
        // ---- load B tile, duplicated: BsDup[c>>3][k*8 + (c&7)] = (b,b)
#pragma unroll
        for (int i = 0; i < 4; i++) {
            int idx = (i * 128 + tid) * 4;   // 0..2044 step 4
            int kk  = idx >> 6;
            int cc  = idx & 63;
            float4 v = *(const float4*)(w + (size_t)(kb + kk) * N_DIM + cc);
            unsigned long long* dst = &BsDup[cc >> 3][kk * 8 + (cc & 7)];
            dst[0] = dup2(v.x);
            dst[1] = dup2(v.y);
            dst[2] = dup2(v.z);
            dst[3] = dup2(v.w);
        }
        __syncthreads();

#pragma unroll
        for (int k = 0; k < BK; k++) {
            // a pairs: 8 rows -> 4 packed (row2i,row2i+1) f32x2 values
            ulonglong2 aA = *(const ulonglong2*)&As[k][ty * 8];
            ulonglong2 aB = *(const ulonglong2*)&As[k][ty * 8 + 4];
            unsigned long long ap0 = aA.x, ap1 = aA.y, ap2 = aB.x, ap3 = aB.y;
            // b dups: 8 duplicated values, conflict-free group layout
            unsigned long long bd[8];
            *(ulonglong2*)&bd[0] = *(const ulonglong2*)&BsDup[tx][k * 8 + 0];
            *(ulonglong2*)&bd[2] = *(const ulonglong2*)&BsDup[tx][k * 8 + 2];
            *(ulonglong2*)&bd[4] = *(const ulonglong2*)&BsDup[tx][k * 8 + 4];
            *(ulonglong2*)&bd[6] = *(const ulonglong2*)&BsDup[tx][k * 8 + 6];
#pragma unroll
            for (int j = 0; j < 8; j++) {
                fma_f32x2(acc2[0][j], ap0, bd[j]);
                fma_f32x2(acc2[1][j], ap1, bd[j]);
                fma_f32x2(acc2[2][j], ap2, bd[j]);
                fma_f32x2(acc2[3][j], ap3, bd[j]);
            }
        }
        __syncthreads();
    }

    // ---- store pre_sup (unpack lo/hi halves to rows 2*i2 / 2*i2+1)
#pragma unroll
    for (int i2 = 0; i2 < 4; i2++) {
        int gr0 = rowBase + ty * 8 + 2 * i2;
        int gr1 = gr0 + 1;
        float lo[8], hi[8];
#pragma unroll
        for (int j = 0; j < 8; j++) {
            lo[j] = __uint_as_float((unsigned int)(acc2[i2][j] & 0xffffffffull));
            hi[j] = __uint_as_float((unsigned int)(acc2[i2][j] >> 32));
        }
        if (gr0 < M) {
            *(float4*)(g_pre + (size_t)gr0 * N_DIM + tx * 8)     = *(float4*)&lo[0];
            *(float4*)(g_pre + (size_t)gr0 * N_DIM + tx * 8 + 4) = *(float4*)&lo[4];
        }
        if (gr1 < M) {
            *(float4*)(g_pre + (size_t)gr1 * N_DIM + tx * 8)     = *(float4*)&hi[0];
            *(float4*)(g_pre + (size_t)gr1 * N_DIM + tx * 8 + 4) = *(float4*)&hi[4];
        }
    }
}

// ---------------------------------------------------------------------------
// Kernel 2: out[r, :] = bias[:]  (initialize before scatter-add)
// ---------------------------------------------------------------------------
__global__ void bias_init_kernel(float* __restrict__ out,
                                 const float* __restrict__ bias, int n4)
{
    int idx = blockIdx.x * blockDim.x + threadIdx.x;
    if (idx >= n4) return;
    int c4 = (idx & 15) * 4;   // column quad within the 64-wide row
    float4 b = *(const float4*)(bias + c4);
    *(float4*)(out + (size_t)idx * 4) = b;
}

// ---------------------------------------------------------------------------
// Kernel 3: scatter  out[rows[e], :] += vals[e] * pre_sup[cols[e], :]
// One thread per (edge, column-quad): 16 threads/edge, vectorized red.add.v4
// ---------------------------------------------------------------------------
__device__ __forceinline__ void red_add_v4(float* addr, float4 v)
{
    asm volatile("red.global.add.v4.f32 [%0], {%1, %2, %3, %4};"
                 :: "l"(addr), "f"(v.x), "f"(v.y), "f"(v.z), "f"(v.w)
                 : "memory");
}

__global__ void scatter_kernel(const void* __restrict__ rows_p,
                               const void* __restrict__ cols_p,
                               const float* __restrict__ vals,
                               float* __restrict__ out, int E)
{
    int idx = blockIdx.x * blockDim.x + threadIdx.x;
    int e = idx >> 4;
    if (e >= E) return;
    int q = idx & 15;

    int r, c;
    if (g_idx64) {
        r = (int)((const long long*)rows_p)[e];
        c = (int)((const long long*)cols_p)[e];
    } else {
        r = ((const int*)rows_p)[e];
        c = ((const int*)cols_p)[e];
    }
    float v = vals[e];

    float4 p = *(const float4*)(g_pre + (size_t)c * N_DIM + q * 4);
    float4 g = make_float4(p.x * v, p.y * v, p.z * v, p.w * v);
    red_add_v4(out + (size_t)r * N_DIM + q * 4, g);
}

// ---------------------------------------------------------------------------
// Kernel 4: in-place ReLU
// ---------------------------------------------------------------------------
__global__ void relu_kernel(float* __restrict__ out, int n4)
{
    int idx = blockIdx.x * blockDim.x + threadIdx.x;
    if (idx >= n4) return;
    float4 v = *(float4*)(out + (size_t)idx * 4);
    v.x = fmaxf(v.x, 0.f);
    v.y = fmaxf(v.y, 0.f);
    v.z = fmaxf(v.z, 0.f);
    v.w = fmaxf(v.w, 0.f);
    *(float4*)(out + (size_t)idx * 4) = v;
}

// ---------------------------------------------------------------------------
// Launch
// Inputs (metadata order):
//   0: x            float32 [N, 256]
//   1: support_rows int32/int64 [E]
//   2: support_cols int32/int64 [E]
//   3: support_vals float32 [E]
//   4: weight       float32 [256, 64]
//   5: bias         float32 [64]
// Output: float32 [N, 64]
// ---------------------------------------------------------------------------
extern "C" void kernel_launch(void* const* d_in, const int* in_sizes, int n_in,
                              void* d_out, int out_size)
{
    const float* x    = (const float*)d_in[0];
    const void*  rows = d_in[1];
    const void*  cols = d_in[2];
    const float* vals = (const float*)d_in[3];
    const float* w    = (const float*)d_in[4];
    const float* bias = (const float*)d_in[5];
    float*       out  = (float*)d_out;

    const int N = in_sizes[0] / K_DIM;
    const int E = in_sizes[1];
    const int n4 = N * N_DIM / 4;   // float4 count of output

    set_flag_kernel<<<1, 1>>>();
    detect_idx_kernel<<<16, 256>>>((const unsigned int*)rows, E);
    gemm_kernel<<<(N + BM - 1) / BM, 128>>>(x, w, N);
    bias_init_kernel<<<(n4 + 255) / 256, 256>>>(out, bias, n4);
    scatter_kernel<<<((E * 16) + 255) / 256, 256>>>(rows, cols, vals, out, E);
    relu_kernel<<<(n4 + 255) / 256, 256>>>(out, n4);
}

// round 5
// speedup vs baseline: 1.4086x; 1.4086x over previous
#include <cuda_runtime.h>
#include <cuda_bf16.h>
#include <cstdint>

// Problem constants (fixed by the dataset)
#define K_DIM 256
#define N_DIM 64
#define MAX_NODES 100000

// Scratch for pre_sup = X @ W  (no cudaMalloc allowed)
__device__ float g_pre[(size_t)MAX_NODES * N_DIM];
// Index-dtype flag: 1 if indices are int64, 0 if int32
__device__ int g_idx64;

// ===========================================================================
// Kernel 0: detect index dtype. Single block, deterministic: always writes
// the flag. int64 values < 2^31 have zero high words; int32 index data at
// odd 32-bit positions is (almost surely) nonzero somewhere in 4096 samples.
// ===========================================================================
__global__ void detect_idx_kernel(const unsigned int* __restrict__ rows_u32, int E)
{
    __shared__ int any_nonzero;
    if (threadIdx.x == 0) any_nonzero = 0;
    __syncthreads();
    int n = E < 4096 ? E : 4096;
    for (int i = threadIdx.x; i < n; i += blockDim.x)
        if (rows_u32[2 * i + 1] != 0u) any_nonzero = 1;   // benign smem race
    __syncthreads();
    if (threadIdx.x == 0) g_idx64 = any_nonzero ? 0 : 1;
}

// ===========================================================================
// Kernel 1: GEMM  pre_sup[M,64] = X[M,256] @ W[256,64] via mma.sync bf16x3.
//
// fp32 ~= hi + lo (bf16 each). D = Xh*Wh + Xh*Wl + Xl*Wh (drop Xl*Wl ~2^-18).
//
// CTA: 256 threads = 8 warps; warp w owns rows [cta*128 + w*16, +16).
// mma.sync.aligned.m16n8k16.row.col.f32.bf16.bf16.f32
//   A frag (16x16, row-major): thread q=lane>>2, t=lane&3 holds
//     a0=(q, 2t..2t+1) a1=(q+8, 2t..) a2=(q, 2t+8..) a3=(q+8, 2t+8..)
//   B frag (16x8, col-major): b0=(k=2t..2t+1, n=q), b1=(k=2t+8.., n=q)
//   D frag: c0=(q, 2t) c1=(q, 2t+1) c2=(q+8, 2t) c3=(q+8, 2t+1)
//
// W staged in smem per K-half (128 k) as u64 words:
//   ws[n*68 + kstep*8 + half*4 + t] = { lo16(k+1),lo16(k) , hi16(k+1),hi16(k) }
//   (low u32 = hi-pair, high u32 = lo-pair), k = kstep*16 + half*8 + 2t.
// Row stride 68 u64 = 544 B == 32 mod 128 -> LDS.64 is conflict-free 2-phase.
// ===========================================================================
#define WS_STRIDE 68   // u64 per n-row

__device__ __forceinline__ void mma_bf16(float* d, uint32_t a0, uint32_t a1,
                                         uint32_t a2, uint32_t a3,
                                         uint32_t b0, uint32_t b1)
{
    asm volatile(
        "mma.sync.aligned.m16n8k16.row.col.f32.bf16.bf16.f32 "
        "{%0, %1, %2, %3}, {%4, %5, %6, %7}, {%8, %9}, {%0, %1, %2, %3};"
        : "+f"(d[0]), "+f"(d[1]), "+f"(d[2]), "+f"(d[3])
        : "r"(a0), "r"(a1), "r"(a2), "r"(a3), "r"(b0), "r"(b1));
}

__device__ __forceinline__ void split_pair(float x0, float x1,
                                           uint32_t& hi, uint32_t& lo)
{
    __nv_bfloat16 h0 = __float2bfloat16(x0);
    __nv_bfloat16 h1 = __float2bfloat16(x1);
    __nv_bfloat162 hp = __halves2bfloat162(h0, h1);
    __nv_bfloat162 lp = __halves2bfloat162(
        __float2bfloat16(x0 - __bfloat162float(h0)),
        __float2bfloat16(x1 - __bfloat162float(h1)));
    hi = *(uint32_t*)&hp;
    lo = *(uint32_t*)&lp;
}

__global__ void __launch_bounds__(256) gemm_mma_kernel(
    const float* __restrict__ x, const float* __restrict__ w, int M)
{
    __shared__ unsigned long long ws[64 * WS_STRIDE];   // 34816 B

    const int tid  = threadIdx.x;
    const int wid  = tid >> 5;
    const int lane = tid & 31;
    const int q = lane >> 2;      // group id
    const int t = lane & 3;       // thread-in-group

    const int warp_m = blockIdx.x * 128 + wid * 16;
    const int row0 = warp_m + q;
    const int row1 = row0 + 8;
    const int row0c = row0 < M ? row0 : 0;   // clamp for loads; stores masked
    const int row1c = row1 < M ? row1 : 0;
    const float* xr0 = x + (size_t)row0c * K_DIM;
    const float* xr1 = x + (size_t)row1c * K_DIM;

    float acc[8][4];
#pragma unroll
    for (int j = 0; j < 8; j++)
#pragma unroll
        for (int i = 0; i < 4; i++) acc[j][i] = 0.f;

#pragma unroll 1
    for (int stage = 0; stage < 2; stage++) {
        // ---- stage W K-half into smem (coalesced: n fastest)
#pragma unroll 1
        for (int idx = tid; idx < 4096; idx += 256) {
            int n = idx & 63;
            int p = idx >> 6;                   // k-pair 0..63
            int k = stage * 128 + p * 2;
            float w0 = w[(size_t)k * N_DIM + n];
            float w1 = w[(size_t)(k + 1) * N_DIM + n];
            uint32_t hi, lo;
            split_pair(w0, w1, hi, lo);
            int kstep = p >> 3, pp = p & 7;
            ws[n * WS_STRIDE + kstep * 8 + (pp >> 2) * 4 + (pp & 3)] =
                ((unsigned long long)lo << 32) | (unsigned long long)hi;
        }
        __syncthreads();

#pragma unroll 1
        for (int ks = 0; ks < 8; ks++) {
            const int k0 = stage * 128 + ks * 16;
            // ---- A fragments: 4 float2 loads + split
            float2 xa = *(const float2*)(xr0 + k0 + 2 * t);
            float2 xc = *(const float2*)(xr1 + k0 + 2 * t);
            float2 xb = *(const float2*)(xr0 + k0 + 2 * t + 8);
            float2 xd = *(const float2*)(xr1 + k0 + 2 * t + 8);
            uint32_t ah0, al0, ah1, al1, ah2, al2, ah3, al3;
            split_pair(xa.x, xa.y, ah0, al0);
            split_pair(xc.x, xc.y, ah1, al1);
            split_pair(xb.x, xb.y, ah2, al2);
            split_pair(xd.x, xd.y, ah3, al3);

#pragma unroll
            for (int j = 0; j < 8; j++) {
                const int n = j * 8 + q;
                unsigned long long w0 = ws[n * WS_STRIDE + ks * 8 + t];
                unsigned long long w1 = ws[n * WS_STRIDE + ks * 8 + 4 + t];
                uint32_t b0h = (uint32_t)w0, b0l = (uint32_t)(w0 >> 32);
                uint32_t b1h = (uint32_t)w1, b1l = (uint32_t)(w1 >> 32);
                mma_bf16(acc[j], ah0, ah1, ah2, ah3, b0h, b1h);  // hh
                mma_bf16(acc[j], ah0, ah1, ah2, ah3, b0l, b1l);  // hl
                mma_bf16(acc[j], al0, al1, al2, al3, b0h, b1h);  // lh
            }
        }
        __syncthreads();
    }

    // ---- epilogue: D frags -> g_pre
#pragma unroll
    for (int j = 0; j < 8; j++) {
        int c = j * 8 + 2 * t;
        if (row0 < M)
            *(float2*)(g_pre + (size_t)row0 * N_DIM + c) =
                make_float2(acc[j][0], acc[j][1]);
        if (row1 < M)
            *(float2*)(g_pre + (size_t)row1 * N_DIM + c) =
                make_float2(acc[j][2], acc[j][3]);
    }
}

// ===========================================================================
// Kernel 2: out[r, :] = bias[:]  (initialize before scatter-add)
// ===========================================================================
__global__ void bias_init_kernel(float* __restrict__ out,
                                 const float* __restrict__ bias, int n4)
{
    int idx = blockIdx.x * blockDim.x + threadIdx.x;
    if (idx >= n4) return;
    int c4 = (idx & 15) * 4;
    float4 b = *(const float4*)(bias + c4);
    *(float4*)(out + (size_t)idx * 4) = b;
}

// ===========================================================================
// Kernel 3: scatter  out[rows[e], :] += vals[e] * pre_sup[cols[e], :]
// One thread per (edge, column-quad): 16 threads/edge, vectorized red.add.v4
// ===========================================================================
__device__ __forceinline__ void red_add_v4(float* addr, float4 v)
{
    asm volatile("red.global.add.v4.f32 [%0], {%1, %2, %3, %4};"
                 :: "l"(addr), "f"(v.x), "f"(v.y), "f"(v.z), "f"(v.w)
                 : "memory");
}

__global__ void scatter_kernel(const void* __restrict__ rows_p,
                               const void* __restrict__ cols_p,
                               const float* __restrict__ vals,
                               float* __restrict__ out, int E)
{
    int idx = blockIdx.x * blockDim.x + threadIdx.x;
    int e = idx >> 4;
    if (e >= E) return;
    int q = idx & 15;

    int r, c;
    if (g_idx64) {
        r = (int)((const long long*)rows_p)[e];
        c = (int)((const long long*)cols_p)[e];
    } else {
        r = ((const int*)rows_p)[e];
        c = ((const int*)cols_p)[e];
    }
    float v = vals[e];

    float4 p = *(const float4*)(g_pre + (size_t)c * N_DIM + q * 4);
    float4 g = make_float4(p.x * v, p.y * v, p.z * v, p.w * v);
    red_add_v4(out + (size_t)r * N_DIM + q * 4, g);
}

// ===========================================================================
// Kernel 4: in-place ReLU
// ===========================================================================
__global__ void relu_kernel(float* __restrict__ out, int n4)
{
    int idx = blockIdx.x * blockDim.x + threadIdx.x;
    if (idx >= n4) return;
    float4 v = *(float4*)(out + (size_t)idx * 4);
    v.x = fmaxf(v.x, 0.f);
    v.y = fmaxf(v.y, 0.f);
    v.z = fmaxf(v.z, 0.f);
    v.w = fmaxf(v.w, 0.f);
    *(float4*)(out + (size_t)idx * 4) = v;
}

// ===========================================================================
// Launch
// Inputs (metadata order):
//   0: x            float32 [N, 256]
//   1: support_rows int32/int64 [E]
//   2: support_cols int32/int64 [E]
//   3: support_vals float32 [E]
//   4: weight       float32 [256, 64]
//   5: bias         float32 [64]
// Output: float32 [N, 64]
// ===========================================================================
extern "C" void kernel_launch(void* const* d_in, const int* in_sizes, int n_in,
                              void* d_out, int out_size)
{
    const float* x    = (const float*)d_in[0];
    const void*  rows = d_in[1];
    const void*  cols = d_in[2];
    const float* vals = (const float*)d_in[3];
    const float* w    = (const float*)d_in[4];
    const float* bias = (const float*)d_in[5];
    float*       out  = (float*)d_out;

    const int N = in_sizes[0] / K_DIM;
    const int E = in_sizes[1];
    const int n4 = N * N_DIM / 4;

    detect_idx_kernel<<<1, 1024>>>((const unsigned int*)rows, E);
    gemm_mma_kernel<<<(N + 127) / 128, 256>>>(x, w, N);
    bias_init_kernel<<<(n4 + 255) / 256, 256>>>(out, bias, n4);
    scatter_kernel<<<((E * 16) + 255) / 256, 256>>>(rows, cols, vals, out, E);
    relu_kernel<<<(n4 + 255) / 256, 256>>>(out, n4);
}

// round 6
// speedup vs baseline: 1.6352x; 1.1609x over previous
#include <cuda_runtime.h>
#include <cuda_bf16.h>
#include <cstdint>

// Problem constants (fixed by the dataset)
#define K_DIM 256
#define N_DIM 64
#define MAX_NODES 100000
#define MAX_EDGES 1310720
#define SCAN_BLK 1024
#define MAX_SCAN_BLOCKS ((MAX_NODES + SCAN_BLK - 1) / SCAN_BLK + 2)

// Device scratch (no cudaMalloc allowed)
__device__ float g_pre[(size_t)MAX_NODES * N_DIM];          // X @ W
__device__ int g_idx64;                                      // index dtype flag
__device__ int g_row_cnt[MAX_NODES];                         // counts, then cursor
__device__ int g_row_off[MAX_NODES + 1];                     // CSR offsets
__device__ unsigned long long g_edge_cv[MAX_EDGES];          // packed (val,col)
__device__ int g_scan_part[MAX_SCAN_BLOCKS];                 // scan partials

// ===========================================================================
// Kernel 0: detect index dtype. int64 values < 2^31 have zero high words.
// ===========================================================================
__global__ void detect_idx_kernel(const unsigned int* __restrict__ rows_u32, int E)
{
    __shared__ int any_nonzero;
    if (threadIdx.x == 0) any_nonzero = 0;
    __syncthreads();
    int n = E < 4096 ? E : 4096;
    for (int i = threadIdx.x; i < n; i += blockDim.x)
        if (rows_u32[2 * i + 1] != 0u) any_nonzero = 1;   // benign smem race
    __syncthreads();
    if (threadIdx.x == 0) g_idx64 = any_nonzero ? 0 : 1;
}

__device__ __forceinline__ int load_idx(const void* p, int e)
{
    return g_idx64 ? (int)((const long long*)p)[e] : ((const int*)p)[e];
}

// ===========================================================================
// GEMM  pre_sup[M,64] = X[M,256] @ W[256,64] via mma.sync bf16x3.
// (unchanged from R5 — see that round for layout notes)
// ===========================================================================
#define WS_STRIDE 68   // u64 per n-row

__device__ __forceinline__ void mma_bf16(float* d, uint32_t a0, uint32_t a1,
                                         uint32_t a2, uint32_t a3,
                                         uint32_t b0, uint32_t b1)
{
    asm volatile(
        "mma.sync.aligned.m16n8k16.row.col.f32.bf16.bf16.f32 "
        "{%0, %1, %2, %3}, {%4, %5, %6, %7}, {%8, %9}, {%0, %1, %2, %3};"
        : "+f"(d[0]), "+f"(d[1]), "+f"(d[2]), "+f"(d[3])
        : "r"(a0), "r"(a1), "r"(a2), "r"(a3), "r"(b0), "r"(b1));
}

__device__ __forceinline__ void split_pair(float x0, float x1,
                                           uint32_t& hi, uint32_t& lo)
{
    __nv_bfloat16 h0 = __float2bfloat16(x0);
    __nv_bfloat16 h1 = __float2bfloat16(x1);
    __nv_bfloat162 hp = __halves2bfloat162(h0, h1);
    __nv_bfloat162 lp = __halves2bfloat162(
        __float2bfloat16(x0 - __bfloat162float(h0)),
        __float2bfloat16(x1 - __bfloat162float(h1)));
    hi = *(uint32_t*)&hp;
    lo = *(uint32_t*)&lp;
}

__global__ void __launch_bounds__(256) gemm_mma_kernel(
    const float* __restrict__ x, const float* __restrict__ w, int M)
{
    __shared__ unsigned long long ws[64 * WS_STRIDE];

    const int tid  = threadIdx.x;
    const int wid  = tid >> 5;
    const int lane = tid & 31;
    const int q = lane >> 2;
    const int t = lane & 3;

    const int warp_m = blockIdx.x * 128 + wid * 16;
    const int row0 = warp_m + q;
    const int row1 = row0 + 8;
    const int row0c = row0 < M ? row0 : 0;
    const int row1c = row1 < M ? row1 : 0;
    const float* xr0 = x + (size_t)row0c * K_DIM;
    const float* xr1 = x + (size_t)row1c * K_DIM;

    float acc[8][4];
#pragma unroll
    for (int j = 0; j < 8; j++)
#pragma unroll
        for (int i = 0; i < 4; i++) acc[j][i] = 0.f;

#pragma unroll 1
    for (int stage = 0; stage < 2; stage++) {
#pragma unroll 1
        for (int idx = tid; idx < 4096; idx += 256) {
            int n = idx & 63;
            int p = idx >> 6;
            int k = stage * 128 + p * 2;
            float w0 = w[(size_t)k * N_DIM + n];
            float w1 = w[(size_t)(k + 1) * N_DIM + n];
            uint32_t hi, lo;
            split_pair(w0, w1, hi, lo);
            int kstep = p >> 3, pp = p & 7;
            ws[n * WS_STRIDE + kstep * 8 + (pp >> 2) * 4 + (pp & 3)] =
                ((unsigned long long)lo << 32) | (unsigned long long)hi;
        }
        __syncthreads();

#pragma unroll 1
        for (int ks = 0; ks < 8; ks++) {
            const int k0 = stage * 128 + ks * 16;
            float2 xa = *(const float2*)(xr0 + k0 + 2 * t);
            float2 xc = *(const float2*)(xr1 + k0 + 2 * t);
            float2 xb = *(const float2*)(xr0 + k0 + 2 * t + 8);
            float2 xd = *(const float2*)(xr1 + k0 + 2 * t + 8);
            uint32_t ah0, al0, ah1, al1, ah2, al2, ah3, al3;
            split_pair(xa.x, xa.y, ah0, al0);
            split_pair(xc.x, xc.y, ah1, al1);
            split_pair(xb.x, xb.y, ah2, al2);
            split_pair(xd.x, xd.y, ah3, al3);

#pragma unroll
            for (int j = 0; j < 8; j++) {
                const int n = j * 8 + q;
                unsigned long long w0 = ws[n * WS_STRIDE + ks * 8 + t];
                unsigned long long w1 = ws[n * WS_STRIDE + ks * 8 + 4 + t];
                uint32_t b0h = (uint32_t)w0, b0l = (uint32_t)(w0 >> 32);
                uint32_t b1h = (uint32_t)w1, b1l = (uint32_t)(w1 >> 32);
                mma_bf16(acc[j], ah0, ah1, ah2, ah3, b0h, b1h);
                mma_bf16(acc[j], ah0, ah1, ah2, ah3, b0l, b1l);
                mma_bf16(acc[j], al0, al1, al2, al3, b0h, b1h);
            }
        }
        __syncthreads();
    }

#pragma unroll
    for (int j = 0; j < 8; j++) {
        int c = j * 8 + 2 * t;
        if (row0 < M)
            *(float2*)(g_pre + (size_t)row0 * N_DIM + c) =
                make_float2(acc[j][0], acc[j][1]);
        if (row1 < M)
            *(float2*)(g_pre + (size_t)row1 * N_DIM + c) =
                make_float2(acc[j][2], acc[j][3]);
    }
}

// ===========================================================================
// CSR build
// ===========================================================================
__global__ void zero_cnt_kernel(int N)
{
    int i = blockIdx.x * blockDim.x + threadIdx.x;
    if (i < N) g_row_cnt[i] = 0;
}

__global__ void hist_kernel(const void* __restrict__ rows_p, int E)
{
    int e = blockIdx.x * blockDim.x + threadIdx.x;
    if (e >= E) return;
    atomicAdd(&g_row_cnt[load_idx(rows_p, e)], 1);
}

// scan step 1: per-block sums of counts
__global__ void __launch_bounds__(SCAN_BLK) scan_partial_kernel(int N)
{
    __shared__ int warp_sums[32];
    int idx = blockIdx.x * SCAN_BLK + threadIdx.x;
    int v = (idx < N) ? g_row_cnt[idx] : 0;
#pragma unroll
    for (int o = 16; o > 0; o >>= 1) v += __shfl_down_sync(0xffffffffu, v, o);
    if ((threadIdx.x & 31) == 0) warp_sums[threadIdx.x >> 5] = v;
    __syncthreads();
    if (threadIdx.x < 32) {
        int s = warp_sums[threadIdx.x];
#pragma unroll
        for (int o = 16; o > 0; o >>= 1) s += __shfl_down_sync(0xffffffffu, s, o);
        if (threadIdx.x == 0) g_scan_part[blockIdx.x] = s;
    }
}

// scan step 2: serial exclusive scan of block partials (tiny)
__global__ void scan_base_kernel(int nblocks, int N)
{
    if (threadIdx.x == 0 && blockIdx.x == 0) {
        int run = 0;
        for (int b = 0; b < nblocks; b++) {
            int t = g_scan_part[b];
            g_scan_part[b] = run;
            run += t;
        }
        g_row_off[N] = run;   // = E
    }
}

// scan step 3: block-local exclusive scan + base -> offsets and cursor
__global__ void __launch_bounds__(SCAN_BLK) scan_write_kernel(int N)
{
    __shared__ int warp_sums[32];
    int idx = blockIdx.x * SCAN_BLK + threadIdx.x;
    int lane = threadIdx.x & 31;
    int wid = threadIdx.x >> 5;

    int v = (idx < N) ? g_row_cnt[idx] : 0;
    int incl = v;
#pragma unroll
    for (int o = 1; o < 32; o <<= 1) {
        int n = __shfl_up_sync(0xffffffffu, incl, o);
        if (lane >= o) incl += n;
    }
    if (lane == 31) warp_sums[wid] = incl;
    __syncthreads();
    if (wid == 0) {
        int s = (lane < 32) ? warp_sums[lane] : 0;
#pragma unroll
        for (int o = 1; o < 32; o <<= 1) {
            int n = __shfl_up_sync(0xffffffffu, s, o);
            if (lane >= o) s += n;
        }
        warp_sums[lane] = s;
    }
    __syncthreads();
    int warp_base = (wid == 0) ? 0 : warp_sums[wid - 1];
    int excl = g_scan_part[blockIdx.x] + warp_base + incl - v;
    if (idx < N) {
        g_row_off[idx] = excl;
        g_row_cnt[idx] = excl;   // becomes the permute cursor
    }
}

// permute: scatter (col,val) into row-sorted list
__global__ void permute_kernel(const void* __restrict__ rows_p,
                               const void* __restrict__ cols_p,
                               const float* __restrict__ vals, int E)
{
    int e = blockIdx.x * blockDim.x + threadIdx.x;
    if (e >= E) return;
    int r = load_idx(rows_p, e);
    int c = load_idx(cols_p, e);
    unsigned int v = __float_as_uint(vals[e]);
    int pos = atomicAdd(&g_row_cnt[r], 1);
    g_edge_cv[pos] = ((unsigned long long)v << 32) | (unsigned int)c;
}

// ===========================================================================
// Gather-reduce: out[r,:] = relu( sum_e val*pre_sup[col,:] + bias )
// 16 threads per row (thread owns one float4 quad); warp covers 2 rows.
// ===========================================================================
__global__ void __launch_bounds__(256) gather_kernel(
    const float* __restrict__ bias, float* __restrict__ out, int N)
{
    int r = blockIdx.x * 16 + (threadIdx.x >> 4);
    int q = threadIdx.x & 15;
    if (r >= N) return;

    int i   = g_row_off[r];
    int end = g_row_off[r + 1];

    float4 acc = make_float4(0.f, 0.f, 0.f, 0.f);
    for (; i < end; i++) {
        unsigned long long cv = g_edge_cv[i];
        int c   = (int)(unsigned int)cv;
        float v = __uint_as_float((unsigned int)(cv >> 32));
        float4 p = *(const float4*)(g_pre + (size_t)c * N_DIM + q * 4);
        acc.x = fmaf(v, p.x, acc.x);
        acc.y = fmaf(v, p.y, acc.y);
        acc.z = fmaf(v, p.z, acc.z);
        acc.w = fmaf(v, p.w, acc.w);
    }

    float4 b = *(const float4*)(bias + q * 4);
    float4 o;
    o.x = fmaxf(acc.x + b.x, 0.f);
    o.y = fmaxf(acc.y + b.y, 0.f);
    o.z = fmaxf(acc.z + b.z, 0.f);
    o.w = fmaxf(acc.w + b.w, 0.f);
    *(float4*)(out + (size_t)r * N_DIM + q * 4) = o;
}

// ===========================================================================
// Launch
// Inputs: 0:x f32[N,256]  1:rows i32/i64[E]  2:cols i32/i64[E]
//         3:vals f32[E]   4:weight f32[256,64]  5:bias f32[64]
// Output: f32 [N, 64]
// ===========================================================================
extern "C" void kernel_launch(void* const* d_in, const int* in_sizes, int n_in,
                              void* d_out, int out_size)
{
    const float* x    = (const float*)d_in[0];
    const void*  rows = d_in[1];
    const void*  cols = d_in[2];
    const float* vals = (const float*)d_in[3];
    const float* w    = (const float*)d_in[4];
    const float* bias = (const float*)d_in[5];
    float*       out  = (float*)d_out;

    const int N = in_sizes[0] / K_DIM;
    const int E = in_sizes[1];
    const int scan_blocks = (N + SCAN_BLK - 1) / SCAN_BLK;

    detect_idx_kernel<<<1, 1024>>>((const unsigned int*)rows, E);
    gemm_mma_kernel<<<(N + 127) / 128, 256>>>(x, w, N);
    zero_cnt_kernel<<<(N + 1023) / 1024, 1024>>>(N);
    hist_kernel<<<(E + 511) / 512, 512>>>(rows, E);
    scan_partial_kernel<<<scan_blocks, SCAN_BLK>>>(N);
    scan_base_kernel<<<1, 32>>>(scan_blocks, N);
    scan_write_kernel<<<scan_blocks, SCAN_BLK>>>(N);
    permute_kernel<<<(E + 511) / 512, 512>>>(rows, cols, vals, E);
    gather_kernel<<<(N + 15) / 16, 256>>>(bias, out, N);
}